// round 7
// baseline (speedup 1.0000x reference)
#include <cuda_runtime.h>
#include <cuda_bf16.h>
#include <cstdint>
#include <cstddef>

// Problem constants (match reference)
#define N_NODES 50000
#define N_EDGES 800000
#define D_IN    128
#define D_HID   256
#define D_OUT   128

// ---------------------------------------------------------------------------
// Pipeline (6 launches; g_cnt is self-cleaning across graph replays):
//   count  (+ inline weight pre-products on first 49 blocks)
//   scan   -> rowoff, cursor, invdeg, flag; zeroes g_cnt for next replay
//   fill   -> CSR adjacency
//   gather1: m1[n] = invdeg[n] * sum x[s]
//   gather2: A2[n] = invdeg[n] * sum m1[s]
//   gemm:   out = A2@U1^T + m1@U2^T + x@U3^T + c + flag*d  (mma.sync bf16 hi/lo)
// ---------------------------------------------------------------------------

// Device scratch
__device__ int   g_cnt[N_NODES];          // zeroed at module load; scan re-zeroes
__device__ int   g_rowoff[N_NODES + 1];
__device__ int   g_cursor[N_NODES];
__device__ int   g_eadj[N_EDGES];
__device__ float g_invdeg[N_NODES];
__device__ float g_flag[N_NODES];         // 1.0 if deg>0 else 0.0
__device__ float g_m1[(size_t)N_NODES * 128];
__device__ float g_A2[(size_t)N_NODES * 128];
__device__ uint4 g_Upk[128 * 24 * 4];     // fragment-packed U (hi/lo)
__device__ float g_c[128];
__device__ float g_d[128];

// ---------------------------------------------------------------------------
// mma helpers
// ---------------------------------------------------------------------------
__device__ __forceinline__ void mma16816(float* d, const uint32_t* a, const uint32_t* b) {
    asm volatile(
        "mma.sync.aligned.m16n8k16.row.col.f32.bf16.bf16.f32 "
        "{%0,%1,%2,%3}, {%4,%5,%6,%7}, {%8,%9}, {%0,%1,%2,%3};"
        : "+f"(d[0]), "+f"(d[1]), "+f"(d[2]), "+f"(d[3])
        : "r"(a[0]), "r"(a[1]), "r"(a[2]), "r"(a[3]), "r"(b[0]), "r"(b[1]));
}
__device__ __forceinline__ void split2(float2 v, uint32_t& hi, uint32_t& lo) {
    __nv_bfloat162 h = __float22bfloat162_rn(v);
    float2 hv = __bfloat1622float2(h);
    __nv_bfloat162 l = __float22bfloat162_rn(make_float2(v.x - hv.x, v.y - hv.y));
    hi = *reinterpret_cast<uint32_t*>(&h);
    lo = *reinterpret_cast<uint32_t*>(&l);
}
__device__ __forceinline__ uint32_t packbf2(float a, float b) {
    __nv_bfloat162 h = __float22bfloat162_rn(make_float2(a, b));
    return *reinterpret_cast<uint32_t*>(&h);
}

// Per-block idx-dtype detection (all blocks agree on random data).
__device__ __forceinline__ int detect_idx64_block(const void* eidx) {
    __shared__ int s_idx64;
    if (threadIdx.x < 32) {
        const long long* p = (const long long*)eidx;
        int ok = 1;
        #pragma unroll
        for (int i = 0; i < 16; ++i) {
            long long v = p[threadIdx.x * 16 + i];
            ok &= (v >= 0 && v < (long long)N_NODES);
        }
        unsigned m = __ballot_sync(0xffffffffu, ok);
        if (threadIdx.x == 0) s_idx64 = (m == 0xffffffffu) ? 1 : 0;
    }
    __syncthreads();
    return s_idx64;
}

// ---------------------------------------------------------------------------
// Weight pre-product work item (one of 128*96 + 128 items)
// Upk[((n*24)+ktg)*4+tq] = {hi(k0,k0+1), hi(k0+8,k0+9), lo(...), lo(...)},
// k0 = (ktg%8)*16 + 2*tq, seg = ktg/8 -> U1/U2/U3.
// ---------------------------------------------------------------------------
__device__ void weight_item(int tid,
                            const float* __restrict__ Wl1,
                            const float* __restrict__ Wr1,
                            const float* __restrict__ Wl2,
                            const float* __restrict__ Wr2,
                            const float* __restrict__ b1,
                            const float* __restrict__ b2) {
    if (tid < 128 * 96) {
        const int n   = tid / 96;
        const int rem = tid - n * 96;
        const int ktg = rem >> 2;
        const int tq  = rem & 3;
        const int seg = ktg >> 3;
        const int k0  = (ktg & 7) * 16 + 2 * tq;

        float u[4] = {0.f, 0.f, 0.f, 0.f};
        const float* A1 = Wl2 + (size_t)n * 256;
        const float* A2 = Wr2 + (size_t)n * 256;
        #pragma unroll 4
        for (int t = 0; t < 256; ++t) {
            const float wl2 = A1[t];
            const float wr2 = A2[t];
            const float* rl = Wl1 + (size_t)t * 128 + k0;
            const float* rr = Wr1 + (size_t)t * 128 + k0;
            if (seg == 0) {
                u[0] += wl2 * rl[0]; u[1] += wl2 * rl[1];
                u[2] += wl2 * rl[8]; u[3] += wl2 * rl[9];
            } else if (seg == 1) {
                u[0] += wl2 * rr[0] + wr2 * rl[0];
                u[1] += wl2 * rr[1] + wr2 * rl[1];
                u[2] += wl2 * rr[8] + wr2 * rl[8];
                u[3] += wl2 * rr[9] + wr2 * rl[9];
            } else {
                u[0] += wr2 * rr[0]; u[1] += wr2 * rr[1];
                u[2] += wr2 * rr[8]; u[3] += wr2 * rr[9];
            }
        }
        uint32_t h0 = packbf2(u[0], u[1]);
        uint32_t h1 = packbf2(u[2], u[3]);
        float r0 = u[0] - __bfloat162float(__ushort_as_bfloat16((uint16_t)(h0 & 0xffff)));
        float r1 = u[1] - __bfloat162float(__ushort_as_bfloat16((uint16_t)(h0 >> 16)));
        float r2 = u[2] - __bfloat162float(__ushort_as_bfloat16((uint16_t)(h1 & 0xffff)));
        float r3 = u[3] - __bfloat162float(__ushort_as_bfloat16((uint16_t)(h1 >> 16)));
        g_Upk[tid] = make_uint4(h0, h1, packbf2(r0, r1), packbf2(r2, r3));
    } else if (tid < 128 * 96 + 128) {
        const int a = tid - 128 * 96;
        float c = 0.f, d = 0.f;
        #pragma unroll 4
        for (int k = 0; k < 256; ++k) {
            c += Wr2[a * 256 + k] * b1[k];
            d += Wl2[a * 256 + k] * b1[k];
        }
        g_c[a] = b2[a] + c;
        g_d[a] = d;
    }
}

// ---------------------------------------------------------------------------
// count: histogram of dst + (blocks < 49) weight pre-products
// ---------------------------------------------------------------------------
#define WEIGHT_ITEMS (128 * 96 + 128)
#define WEIGHT_BLOCKS ((WEIGHT_ITEMS + 255) / 256)   // 49

__global__ __launch_bounds__(256)
void count_kernel(const void* __restrict__ eidx,
                  const float* __restrict__ Wl1, const float* __restrict__ Wr1,
                  const float* __restrict__ Wl2, const float* __restrict__ Wr2,
                  const float* __restrict__ b1,  const float* __restrict__ b2) {
    const int idx64 = detect_idx64_block(eidx);
    const int e = blockIdx.x * blockDim.x + threadIdx.x;
    if (e < N_EDGES) {
        int dst;
        if (idx64) dst = (int)((const long long*)eidx)[N_EDGES + e];
        else       dst = ((const int*)eidx)[N_EDGES + e];
        atomicAdd(&g_cnt[dst], 1);
    }
    if (blockIdx.x < WEIGHT_BLOCKS)
        weight_item(blockIdx.x * 256 + threadIdx.x, Wl1, Wr1, Wl2, Wr2, b1, b2);
}

// ---------------------------------------------------------------------------
// scan: offsets/cursor/invdeg/flag; self-cleans g_cnt for the next replay
// ---------------------------------------------------------------------------
#define SCAN_T 1024
#define SCAN_CH 49
__global__ __launch_bounds__(SCAN_T)
void scan_kernel() {
    __shared__ int wsum[32];
    const int t = threadIdx.x;
    const int base = t * SCAN_CH;

    int cnt[SCAN_CH];
    int lsum = 0;
    #pragma unroll 7
    for (int i = 0; i < SCAN_CH; ++i) {
        const int idx = base + i;
        cnt[i] = (idx < N_NODES) ? g_cnt[idx] : 0;
        lsum += cnt[i];
    }

    int v = lsum;
    #pragma unroll
    for (int d = 1; d < 32; d <<= 1) {
        int n = __shfl_up_sync(0xffffffffu, v, d);
        if ((t & 31) >= d) v += n;
    }
    if ((t & 31) == 31) wsum[t >> 5] = v;
    __syncthreads();
    if (t < 32) {
        int w = wsum[t];
        #pragma unroll
        for (int d = 1; d < 32; d <<= 1) {
            int n = __shfl_up_sync(0xffffffffu, w, d);
            if (t >= d) w += n;
        }
        wsum[t] = w;
    }
    __syncthreads();
    int run = v + ((t >= 32) ? wsum[(t >> 5) - 1] : 0) - lsum;

    #pragma unroll 7
    for (int i = 0; i < SCAN_CH; ++i) {
        const int idx = base + i;
        if (idx < N_NODES) {
            const int c = cnt[i];
            g_rowoff[idx] = run;
            g_cursor[idx] = run;
            g_invdeg[idx] = 1.0f / fmaxf((float)c, 1.0f);
            g_flag[idx]   = (c > 0) ? 1.0f : 0.0f;
            g_cnt[idx]    = 0;   // self-clean for next replay
            run += c;
        }
    }
    if (t == SCAN_T - 1) g_rowoff[N_NODES] = N_EDGES;
}

__global__ __launch_bounds__(256)
void fill_csr_kernel(const void* __restrict__ eidx) {
    const int idx64 = detect_idx64_block(eidx);
    const int e = blockIdx.x * blockDim.x + threadIdx.x;
    if (e >= N_EDGES) return;
    int src, dst;
    if (idx64) {
        const long long* ep = (const long long*)eidx;
        src = (int)ep[e]; dst = (int)ep[N_EDGES + e];
    } else {
        const int* ep = (const int*)eidx;
        src = ep[e]; dst = ep[N_EDGES + e];
    }
    const int pos = atomicAdd(&g_cursor[dst], 1);
    g_eadj[pos] = src;
}

// ---------------------------------------------------------------------------
// Gathers: one warp per node, lane owns one float4, unroll 4
// ---------------------------------------------------------------------------
__global__ __launch_bounds__(256)
void gather_kernel(const float* __restrict__ src_feat, float* __restrict__ dst_feat) {
    const int node = (blockIdx.x * blockDim.x + threadIdx.x) >> 5;
    if (node >= N_NODES) return;
    const int lane = threadIdx.x & 31;
    const int beg = g_rowoff[node];
    const int end = g_rowoff[node + 1];
    const float4* f4 = (const float4*)src_feat;

    float4 acc = make_float4(0.f, 0.f, 0.f, 0.f);
    int i = beg;
    for (; i + 4 <= end; i += 4) {
        const int s0 = g_eadj[i];
        const int s1 = g_eadj[i + 1];
        const int s2 = g_eadj[i + 2];
        const int s3 = g_eadj[i + 3];
        float4 v0 = __ldg(&f4[(size_t)s0 * 32 + lane]);
        float4 v1 = __ldg(&f4[(size_t)s1 * 32 + lane]);
        float4 v2 = __ldg(&f4[(size_t)s2 * 32 + lane]);
        float4 v3 = __ldg(&f4[(size_t)s3 * 32 + lane]);
        acc.x += (v0.x + v1.x) + (v2.x + v3.x);
        acc.y += (v0.y + v1.y) + (v2.y + v3.y);
        acc.z += (v0.z + v1.z) + (v2.z + v3.z);
        acc.w += (v0.w + v1.w) + (v2.w + v3.w);
    }
    for (; i < end; ++i) {
        const int s0 = g_eadj[i];
        float4 v0 = __ldg(&f4[(size_t)s0 * 32 + lane]);
        acc.x += v0.x; acc.y += v0.y; acc.z += v0.z; acc.w += v0.w;
    }
    const float w = g_invdeg[node];
    acc.x *= w; acc.y *= w; acc.z *= w; acc.w *= w;
    ((float4*)dst_feat)[(size_t)node * 32 + lane] = acc;
}

// ---------------------------------------------------------------------------
// Tensor-core GEMM: out[M,128] = [A2 | m1 | x] @ U^T + c + flag*d
// CTA 128x128; 8 warps stacked in M (warp = 16 rows x 128 cols) so each A row
// is loaded by exactly one warp. Warp: 1 x 16 m16n8k16 fragments.
// ---------------------------------------------------------------------------
__global__ __launch_bounds__(256)
void mma_gemm_kernel(const float* __restrict__ x, float* __restrict__ out, int M) {
    const int tid  = threadIdx.x;
    const int wid  = tid >> 5;
    const int lane = tid & 31;
    const int g    = lane >> 2;
    const int tq   = lane & 3;
    const int mb   = blockIdx.x * 128 + wid * 16;

    int   rows[2];
    bool  rowok[2];
    float flag[2];
    #pragma unroll
    for (int h = 0; h < 2; ++h) {
        rows[h]  = mb + h * 8 + g;
        rowok[h] = rows[h] < M;
        flag[h]  = rowok[h] ? g_flag[rows[h]] : 0.f;
    }

    float acc[16][4];
    #pragma unroll
    for (int ni = 0; ni < 16; ++ni)
        #pragma unroll
        for (int q = 0; q < 4; ++q) acc[ni][q] = 0.f;

    #pragma unroll 1
    for (int s = 0; s < 3; ++s) {
        const float* Asrc = (s == 0) ? g_A2 : ((s == 1) ? g_m1 : x);

        #pragma unroll 1
        for (int kt = 0; kt < 8; ++kt) {
            const int kk  = kt * 16;
            const int ktg = s * 8 + kt;

            // A fragments (load fp32, split hi/lo)
            uint32_t ah[4], al[4];
            #pragma unroll
            for (int h = 0; h < 2; ++h)
                #pragma unroll
                for (int kh = 0; kh < 2; ++kh) {
                    float2 v = make_float2(0.f, 0.f);
                    if (rowok[h])
                        v = *(const float2*)(Asrc + (size_t)rows[h] * 128
                                             + kk + tq * 2 + kh * 8);
                    split2(v, ah[kh * 2 + h], al[kh * 2 + h]);
                }

            // B fragments + MMAs (all 16 n-tiles)
            #pragma unroll
            for (int ni = 0; ni < 16; ++ni) {
                const int n = ni * 8 + g;
                const uint4 bf = g_Upk[(n * 24 + ktg) * 4 + tq];
                uint32_t bh[2] = {bf.x, bf.y};
                uint32_t bl[2] = {bf.z, bf.w};
                mma16816(acc[ni], ah, bh);
                mma16816(acc[ni], al, bh);
                mma16816(acc[ni], ah, bl);
            }
        }
    }

    #pragma unroll
    for (int ni = 0; ni < 16; ++ni) {
        const int col = ni * 8 + tq * 2;
        const float2 cc = *(const float2*)(g_c + col);
        const float2 dd = *(const float2*)(g_d + col);
        #pragma unroll
        for (int h = 0; h < 2; ++h) {
            if (rowok[h]) {
                float2 o;
                o.x = acc[ni][h * 2 + 0] + cc.x + flag[h] * dd.x;
                o.y = acc[ni][h * 2 + 1] + cc.y + flag[h] * dd.y;
                *(float2*)(out + (size_t)rows[h] * 128 + col) = o;
            }
        }
    }
}

// ---------------------------------------------------------------------------
// Launch (exactly 6 kernels; ncu -s 5 lands on mma_gemm)
// ---------------------------------------------------------------------------
extern "C" void kernel_launch(void* const* d_in, const int* in_sizes, int n_in,
                              void* d_out, int out_size) {
    const float* x    = (const float*)d_in[0];
    const void*  eidx = d_in[1];
    const float* W_l1 = (const float*)d_in[2];
    const float* b_l1 = (const float*)d_in[3];
    const float* W_r1 = (const float*)d_in[4];
    const float* W_l2 = (const float*)d_in[5];
    const float* b_l2 = (const float*)d_in[6];
    const float* W_r2 = (const float*)d_in[7];
    float* out = (float*)d_out;

    float *p_m1, *p_A2;
    cudaGetSymbolAddress((void**)&p_m1, g_m1);
    cudaGetSymbolAddress((void**)&p_A2, g_A2);

    // 1) count (+ weight pre-products)
    count_kernel<<<(N_EDGES + 255) / 256, 256>>>(eidx, W_l1, W_r1, W_l2, W_r2, b_l1, b_l2);
    // 2) scan (also zeroes g_cnt for next replay)
    scan_kernel<<<1, SCAN_T>>>();
    // 3) CSR fill
    fill_csr_kernel<<<(N_EDGES + 255) / 256, 256>>>(eidx);
    // 4-5) gathers
    const unsigned gblocks = (N_NODES * 32 + 255) / 256;
    gather_kernel<<<gblocks, 256>>>(x, p_m1);
    gather_kernel<<<gblocks, 256>>>(p_m1, p_A2);
    // 6) fused tensor-core GEMM
    mma_gemm_kernel<<<(N_NODES + 127) / 128, 256>>>(x, out, N_NODES);
}